// round 8
// baseline (speedup 1.0000x reference)
#include <cuda_runtime.h>
#include <cuda_fp16.h>
#include <cuda_bf16.h>
#include <cstdint>

#define BB 4
#define TT 256
#define UU 128
#define D_ENC 512
#define D_PRED 640
#define HH 512
#define VV 1024
#define EPSV 1e-5f

// Device scratch
__device__ float  g_enc [BB * TT * HH];
__device__ float  g_pred[BB * UU * HH];
__device__ __half g_wout[VV * HH];      // fp16 copy of W_out, [v][h]

// ---------------------------------------------------------------------------
// Fused prep kernel, v2: register-staged double-buffered projections (BK=32).
// blocks [0,128) enc, [128,192) pred, [192,256) W_out convert.
// ---------------------------------------------------------------------------
__device__ __forceinline__ void proj_body(const float* __restrict__ X,
                                          const float* __restrict__ W,
                                          const float* __restrict__ bias,
                                          float* __restrict__ C,
                                          int m0, int n0, int N, int K,
                                          float Xs[2][32][65], float Ws[2][32][65])
{
    const int tid = threadIdx.x;
    const int ty = tid >> 4, tx = tid & 15;
    const int rL = tid >> 5;      // 0..7 (+8 per p)
    const int cL = tid & 31;      // k within chunk

    float xr[8], wr[8];
    #pragma unroll
    for (int p = 0; p < 8; p++) {
        xr[p] = X[(size_t)(m0 + p * 8 + rL) * K + cL];
        wr[p] = W[(size_t)(n0 + p * 8 + rL) * K + cL];
    }

    float acc[4][4];
    #pragma unroll
    for (int i = 0; i < 4; i++)
        #pragma unroll
        for (int j = 0; j < 4; j++) acc[i][j] = 0.f;

    const int NK = K >> 5;
    for (int t = 0; t < NK; t++) {
        const int buf = t & 1;
        #pragma unroll
        for (int p = 0; p < 8; p++) {
            Xs[buf][cL][p * 8 + rL] = xr[p];
            Ws[buf][cL][p * 8 + rL] = wr[p];
        }
        __syncthreads();
        if (t + 1 < NK) {
            const int k0 = (t + 1) << 5;
            #pragma unroll
            for (int p = 0; p < 8; p++) {
                xr[p] = X[(size_t)(m0 + p * 8 + rL) * K + k0 + cL];
                wr[p] = W[(size_t)(n0 + p * 8 + rL) * K + k0 + cL];
            }
        }
        #pragma unroll
        for (int kk = 0; kk < 32; kk++) {
            float a[4], b[4];
            #pragma unroll
            for (int i = 0; i < 4; i++) a[i] = Xs[buf][kk][ty * 4 + i];
            #pragma unroll
            for (int j = 0; j < 4; j++) b[j] = Ws[buf][kk][tx * 4 + j];
            #pragma unroll
            for (int i = 0; i < 4; i++)
                #pragma unroll
                for (int j = 0; j < 4; j++) acc[i][j] = fmaf(a[i], b[j], acc[i][j]);
        }
    }
    #pragma unroll
    for (int i = 0; i < 4; i++)
        #pragma unroll
        for (int j = 0; j < 4; j++) {
            int m = m0 + ty * 4 + i, n = n0 + tx * 4 + j;
            C[(size_t)m * N + n] = acc[i][j] + bias[n];
        }
}

__global__ void __launch_bounds__(256)
prep_kernel(const float* __restrict__ enc_in, const float* __restrict__ pred_in,
            const float* __restrict__ W_enc, const float* __restrict__ b_enc,
            const float* __restrict__ W_pred, const float* __restrict__ b_pred,
            const float* __restrict__ W_out,
            float* __restrict__ enc_out, float* __restrict__ pred_out)
{
    __shared__ float Xs[2][32][65];
    __shared__ float Ws[2][32][65];
    const int blk = blockIdx.x;
    if (blk < 128) {
        proj_body(enc_in, W_enc, b_enc, enc_out,
                  (blk >> 3) * 64, (blk & 7) * 64, HH, D_ENC, Xs, Ws);
    } else if (blk < 192) {
        const int t = blk - 128;
        proj_body(pred_in, W_pred, b_pred, pred_out,
                  (t >> 3) * 64, (t & 7) * 64, HH, D_PRED, Xs, Ws);
    } else {
        const int t = blk - 192;
        const int tid = threadIdx.x;
        #pragma unroll
        for (int j = 0; j < 8; j++) {
            int idx = t * 8192 + j * 1024 + tid * 4;
            float4 v = *reinterpret_cast<const float4*>(W_out + idx);
            __half2 h01 = __floats2half2_rn(v.x, v.y);
            __half2 h23 = __floats2half2_rn(v.z, v.w);
            uint2 pk;
            pk.x = *reinterpret_cast<uint32_t*>(&h01);
            pk.y = *reinterpret_cast<uint32_t*>(&h23);
            *reinterpret_cast<uint2*>(&g_wout[idx]) = pk;
        }
    }
}

// ---------------------------------------------------------------------------
// mma.sync helpers
// ---------------------------------------------------------------------------
__device__ __forceinline__ uint32_t smem_u32(const void* p) {
    return (uint32_t)__cvta_generic_to_shared(p);
}
__device__ __forceinline__ void ldmX4(uint32_t a[4], uint32_t addr) {
    asm volatile("ldmatrix.sync.aligned.m8n8.x4.shared.b16 {%0,%1,%2,%3}, [%4];"
                 : "=r"(a[0]), "=r"(a[1]), "=r"(a[2]), "=r"(a[3]) : "r"(addr));
}
__device__ __forceinline__ void mma16816(float c[4], const uint32_t a[4],
                                         uint32_t b0, uint32_t b1) {
    asm volatile(
        "mma.sync.aligned.m16n8k16.row.col.f32.f16.f16.f32 "
        "{%0,%1,%2,%3}, {%4,%5,%6,%7}, {%8,%9}, {%0,%1,%2,%3};"
        : "+f"(c[0]), "+f"(c[1]), "+f"(c[2]), "+f"(c[3])
        : "r"(a[0]), "r"(a[1]), "r"(a[2]), "r"(a[3]), "r"(b0), "r"(b1));
}
__device__ __forceinline__ void cp16(uint32_t dst, const void* src) {
    asm volatile("cp.async.cg.shared.global [%0], [%1], 16;" :: "r"(dst), "l"(src));
}

// ---------------------------------------------------------------------------
// joint kernel: R6 control flow (2-stage double buffer), B fragments for the
// whole k32 chunk preloaded up front to lengthen LDSM->MMA distance.
// ---------------------------------------------------------------------------
#define A_BYTES   65536
#define B_CHUNK   16384
#define OFF_A     0
#define OFF_B     A_BYTES
#define SMEM_TOTAL (A_BYTES + 2 * B_CHUNK)   // 98304

__global__ void __launch_bounds__(256, 2)
joint_kernel(const float* __restrict__ gamma, const float* __restrict__ beta,
             const float* __restrict__ b_out, float* __restrict__ out)
{
    extern __shared__ __align__(1024) char smem[];
    const uint32_t smemU = smem_u32(smem);
    const uint32_t Bs_u  = smemU + OFF_B;

    const int bt   = blockIdx.x >> 1;
    const int half = blockIdx.x & 1;
    const int bb   = bt >> 8;
    const int tid  = threadIdx.x;
    const int w    = tid >> 5, lane = tid & 31;

    // stage enc/gamma/beta in buf1 region (overwritten later by B chunk kc=1)
    float* encS   = (float*)(smem + OFF_B + B_CHUNK);
    float* gammaS = encS + 512;
    float* betaS  = gammaS + 512;

    // B load lane mapping: 4 cp16 per thread per chunk; swizzle invariant in p
    const int nrL  = tid >> 2;
    const int segL = tid & 3;
    const uint32_t dstL = (uint32_t)(nrL * 64 + ((segL ^ ((nrL >> 1) & 3)) << 4));
    const __half* srcL = g_wout + (size_t)nrL * HH + (segL << 3);

    // ---- issue B chunk 0 (tile 0) load now; overlaps phase 1 compute ----
    #pragma unroll
    for (int p = 0; p < 4; p++)
        cp16(Bs_u + dstL + (uint32_t)(p << 12), srcL + (size_t)(p << 6) * HH);
    asm volatile("cp.async.commit_group;");

    for (int i = tid; i < 512; i += 256) {
        encS[i]   = g_enc[(size_t)bt * HH + i];
        gammaS[i] = gamma[i];
        betaS[i]  = beta[i];
    }
    __syncthreads();

    // ---- Phase 1: A = LN(relu(enc+pred)), fp16, XOR-swizzled rows ----
    #pragma unroll
    for (int r = 0; r < 8; r++) {
        const int u  = r * 8 + w;
        const int ug = half * 64 + u;
        const float* pr = g_pred + ((size_t)(bb * UU + ug)) * HH;
        float v[16];
        float s = 0.f, s2 = 0.f;
        #pragma unroll
        for (int i = 0; i < 16; i++) {
            int h = lane + (i << 5);
            float x = encS[h] + pr[h];
            x = fmaxf(x, 0.f);
            v[i] = x; s += x; s2 += x * x;
        }
        #pragma unroll
        for (int o = 16; o; o >>= 1) {
            s  += __shfl_xor_sync(0xffffffffu, s,  o);
            s2 += __shfl_xor_sync(0xffffffffu, s2, o);
        }
        float mean = s * (1.f / 512.f);
        float var  = fmaxf(s2 * (1.f / 512.f) - mean * mean, 0.f);
        float rstd = rsqrtf(var + EPSV);
        const uint32_t xr = (uint32_t)((u & 7) << 4);
        #pragma unroll
        for (int i = 0; i < 16; i++) {
            int h = lane + (i << 5);
            uint32_t off = (uint32_t)(u * 1024) + ((uint32_t)((h >> 3) << 4) ^ xr)
                         + (uint32_t)((h & 7) << 1);
            *(__half*)(smem + OFF_A + off) =
                __float2half((v[i] - mean) * rstd * gammaS[h] + betaS[h]);
        }
    }

    // ---- Phase 2: GEMM 64x1024x512, nested tiles ----
    const int warpM = w & 1;
    const int warpN = w >> 1;

    const int rowA0 = warpM * 32 + (lane & 15);
    const uint32_t aBase = smemU + OFF_A + (uint32_t)(rowA0 * 1024);
    const uint32_t xorA  = (uint32_t)((rowA0 & 7) << 4);
    const uint32_t klane = (uint32_t)((lane >> 4) << 4);

    const int nLaneRow = (lane & 7) + ((lane >> 4) << 3);
    const int khalf    = (lane >> 3) & 1;
    uint32_t bBase[4], bXor[4];
    #pragma unroll
    for (int j = 0; j < 4; j++) {
        const int n = warpN * 64 + j * 16 + nLaneRow;
        bBase[j] = (uint32_t)(n * 64);
        bXor[j]  = (uint32_t)(((n >> 1) & 3) << 4);
    }

    float acc[2][8][4];
    const size_t outBase = (size_t)bt * (UU * VV) + (size_t)half * 64 * VV;

    for (int no = 0; no < 4; no++) {
        const int n0 = no << 8;
        #pragma unroll
        for (int mi = 0; mi < 2; mi++)
            #pragma unroll
            for (int ni = 0; ni < 8; ni++)
                #pragma unroll
                for (int q = 0; q < 4; q++) acc[mi][ni][q] = 0.f;

        // chunk 0 of this tile is in flight (pre-phase-1 or prior tile tail)
        asm volatile("cp.async.wait_group 0;" ::: "memory");
        __syncthreads();

        for (int kc = 0; kc < 16; kc++) {
            const int buf = kc & 1;
            // prefetch next chunk (kc+1 of this tile, or chunk 0 of next tile)
            if (kc < 15 || no < 3) {
                const int kn  = (kc < 15) ? ((kc + 1) << 5) : 0;
                const int n0l = (kc < 15) ? n0 : (n0 + 256);
                const uint32_t dstBase = Bs_u + (uint32_t)((buf ^ 1) * B_CHUNK) + dstL;
                #pragma unroll
                for (int p = 0; p < 4; p++)
                    cp16(dstBase + (uint32_t)(p << 12),
                         srcL + (size_t)(n0l + (p << 6)) * HH + kn);
                asm volatile("cp.async.commit_group;");
            }

            const int kglob = kc << 5;
            const uint32_t bufB = Bs_u + (uint32_t)(buf * B_CHUNK);

            // ---- preload ALL B fragments for this k32 chunk ----
            uint32_t bf[2][4][4];
            #pragma unroll
            for (int kk2 = 0; kk2 < 2; kk2++) {
                const uint32_t seg16 = (uint32_t)((kk2 << 1) + khalf) << 4;
                #pragma unroll
                for (int j = 0; j < 4; j++)
                    ldmX4(bf[kk2][j], bufB + bBase[j] + (seg16 ^ bXor[j]));
            }
            // ---- per kk2: A loads + MMAs (B already in regs) ----
            #pragma unroll
            for (int kk2 = 0; kk2 < 2; kk2++) {
                const int kk = kk2 << 4;
                const uint32_t aOff = (((uint32_t)((kglob + kk) << 1) + klane) ^ xorA);
                uint32_t a[2][4];
                ldmX4(a[0], aBase + aOff);
                ldmX4(a[1], aBase + 16384u + aOff);
                #pragma unroll
                for (int mi = 0; mi < 2; mi++)
                    #pragma unroll
                    for (int ni = 0; ni < 8; ni++)
                        mma16816(acc[mi][ni], a[mi],
                                 bf[kk2][ni >> 1][(ni & 1) * 2],
                                 bf[kk2][ni >> 1][(ni & 1) * 2 + 1]);
            }
            if (kc < 15) {
                asm volatile("cp.async.wait_group 0;" ::: "memory");
                __syncthreads();
            }
        }

        // epilogue (next tile's chunk-0 load already in flight)
        #pragma unroll
        for (int mi = 0; mi < 2; mi++) {
            const int row = warpM * 32 + mi * 16 + (lane >> 2);
            #pragma unroll
            for (int ni = 0; ni < 8; ni++) {
                const int col = n0 + warpN * 64 + ni * 8 + ((lane & 3) << 1);
                const float2 bo = __ldg(reinterpret_cast<const float2*>(b_out + col));
                float2 v0 = make_float2(acc[mi][ni][0] + bo.x, acc[mi][ni][1] + bo.y);
                float2 v1 = make_float2(acc[mi][ni][2] + bo.x, acc[mi][ni][3] + bo.y);
                *reinterpret_cast<float2*>(out + outBase + (size_t)row * VV + col)       = v0;
                *reinterpret_cast<float2*>(out + outBase + (size_t)(row + 8) * VV + col) = v1;
            }
        }
    }
}

// ---------------------------------------------------------------------------
extern "C" void kernel_launch(void* const* d_in, const int* in_sizes, int n_in,
                              void* d_out, int out_size)
{
    (void)in_sizes; (void)n_in; (void)out_size;
    const float* enc_in  = (const float*)d_in[0];
    const float* pred_in = (const float*)d_in[1];
    const float* W_enc   = (const float*)d_in[2];
    const float* b_enc   = (const float*)d_in[3];
    const float* W_pred  = (const float*)d_in[4];
    const float* b_pred  = (const float*)d_in[5];
    const float* gamma   = (const float*)d_in[6];
    const float* beta    = (const float*)d_in[7];
    const float* W_out   = (const float*)d_in[8];
    const float* b_out   = (const float*)d_in[9];
    float* out = (float*)d_out;

    float* enc_ptr = nullptr;
    float* pred_ptr = nullptr;
    cudaGetSymbolAddress((void**)&enc_ptr,  g_enc);
    cudaGetSymbolAddress((void**)&pred_ptr, g_pred);

    prep_kernel<<<256, 256>>>(enc_in, pred_in, W_enc, b_enc, W_pred, b_pred,
                              W_out, enc_ptr, pred_ptr);

    cudaFuncSetAttribute(joint_kernel, cudaFuncAttributeMaxDynamicSharedMemorySize,
                         SMEM_TOTAL);
    joint_kernel<<<BB * TT * 2, 256, SMEM_TOTAL>>>(gamma, beta, b_out, out);
}

// round 9
// speedup vs baseline: 1.5907x; 1.5907x over previous
#include <cuda_runtime.h>
#include <cuda_fp16.h>
#include <cuda_bf16.h>
#include <cstdint>

#define BB 4
#define TT 256
#define UU 128
#define D_ENC 512
#define D_PRED 640
#define HH 512
#define VV 1024
#define EPSV 1e-5f

// Device scratch
__device__ float  g_enc [BB * TT * HH];
__device__ float  g_pred[BB * UU * HH];
__device__ __half g_wout[VV * HH];      // fp16 copy of W_out, [v][h]

// ---------------------------------------------------------------------------
// Fused prep kernel v2 (kept from R8): register-staged, BK=32 double buffer.
// blocks [0,128) enc, [128,192) pred, [192,256) W_out convert.
// ---------------------------------------------------------------------------
__device__ __forceinline__ void proj_body(const float* __restrict__ X,
                                          const float* __restrict__ W,
                                          const float* __restrict__ bias,
                                          float* __restrict__ C,
                                          int m0, int n0, int N, int K,
                                          float Xs[2][32][65], float Ws[2][32][65])
{
    const int tid = threadIdx.x;
    const int ty = tid >> 4, tx = tid & 15;
    const int rL = tid >> 5;
    const int cL = tid & 31;

    float xr[8], wr[8];
    #pragma unroll
    for (int p = 0; p < 8; p++) {
        xr[p] = X[(size_t)(m0 + p * 8 + rL) * K + cL];
        wr[p] = W[(size_t)(n0 + p * 8 + rL) * K + cL];
    }

    float acc[4][4];
    #pragma unroll
    for (int i = 0; i < 4; i++)
        #pragma unroll
        for (int j = 0; j < 4; j++) acc[i][j] = 0.f;

    const int NK = K >> 5;
    for (int t = 0; t < NK; t++) {
        const int buf = t & 1;
        #pragma unroll
        for (int p = 0; p < 8; p++) {
            Xs[buf][cL][p * 8 + rL] = xr[p];
            Ws[buf][cL][p * 8 + rL] = wr[p];
        }
        __syncthreads();
        if (t + 1 < NK) {
            const int k0 = (t + 1) << 5;
            #pragma unroll
            for (int p = 0; p < 8; p++) {
                xr[p] = X[(size_t)(m0 + p * 8 + rL) * K + k0 + cL];
                wr[p] = W[(size_t)(n0 + p * 8 + rL) * K + k0 + cL];
            }
        }
        #pragma unroll
        for (int kk = 0; kk < 32; kk++) {
            float a[4], b[4];
            #pragma unroll
            for (int i = 0; i < 4; i++) a[i] = Xs[buf][kk][ty * 4 + i];
            #pragma unroll
            for (int j = 0; j < 4; j++) b[j] = Ws[buf][kk][tx * 4 + j];
            #pragma unroll
            for (int i = 0; i < 4; i++)
                #pragma unroll
                for (int j = 0; j < 4; j++) acc[i][j] = fmaf(a[i], b[j], acc[i][j]);
        }
    }
    #pragma unroll
    for (int i = 0; i < 4; i++)
        #pragma unroll
        for (int j = 0; j < 4; j++) {
            int m = m0 + ty * 4 + i, n = n0 + tx * 4 + j;
            C[(size_t)m * N + n] = acc[i][j] + bias[n];
        }
}

__global__ void __launch_bounds__(256)
prep_kernel(const float* __restrict__ enc_in, const float* __restrict__ pred_in,
            const float* __restrict__ W_enc, const float* __restrict__ b_enc,
            const float* __restrict__ W_pred, const float* __restrict__ b_pred,
            const float* __restrict__ W_out,
            float* __restrict__ enc_out, float* __restrict__ pred_out)
{
    __shared__ float Xs[2][32][65];
    __shared__ float Ws[2][32][65];
    const int blk = blockIdx.x;
    if (blk < 128) {
        proj_body(enc_in, W_enc, b_enc, enc_out,
                  (blk >> 3) * 64, (blk & 7) * 64, HH, D_ENC, Xs, Ws);
    } else if (blk < 192) {
        const int t = blk - 128;
        proj_body(pred_in, W_pred, b_pred, pred_out,
                  (t >> 3) * 64, (t & 7) * 64, HH, D_PRED, Xs, Ws);
    } else {
        const int t = blk - 192;
        const int tid = threadIdx.x;
        #pragma unroll
        for (int j = 0; j < 8; j++) {
            int idx = t * 8192 + j * 1024 + tid * 4;
            float4 v = *reinterpret_cast<const float4*>(W_out + idx);
            __half2 h01 = __floats2half2_rn(v.x, v.y);
            __half2 h23 = __floats2half2_rn(v.z, v.w);
            uint2 pk;
            pk.x = *reinterpret_cast<uint32_t*>(&h01);
            pk.y = *reinterpret_cast<uint32_t*>(&h23);
            *reinterpret_cast<uint2*>(&g_wout[idx]) = pk;
        }
    }
}

// ---------------------------------------------------------------------------
// mma.sync helpers
// ---------------------------------------------------------------------------
__device__ __forceinline__ uint32_t smem_u32(const void* p) {
    return (uint32_t)__cvta_generic_to_shared(p);
}
__device__ __forceinline__ void ldmX4(uint32_t a[4], uint32_t addr) {
    asm volatile("ldmatrix.sync.aligned.m8n8.x4.shared.b16 {%0,%1,%2,%3}, [%4];"
                 : "=r"(a[0]), "=r"(a[1]), "=r"(a[2]), "=r"(a[3]) : "r"(addr));
}
__device__ __forceinline__ void mma16816(float c[4], const uint32_t a[4],
                                         uint32_t b0, uint32_t b1) {
    asm volatile(
        "mma.sync.aligned.m16n8k16.row.col.f32.f16.f16.f32 "
        "{%0,%1,%2,%3}, {%4,%5,%6,%7}, {%8,%9}, {%0,%1,%2,%3};"
        : "+f"(c[0]), "+f"(c[1]), "+f"(c[2]), "+f"(c[3])
        : "r"(a[0]), "r"(a[1]), "r"(a[2]), "r"(a[3]), "r"(b0), "r"(b1));
}
__device__ __forceinline__ void cp16(uint32_t dst, const void* src) {
    asm volatile("cp.async.cg.shared.global [%0], [%1], 16;" :: "r"(dst), "l"(src));
}

// ---------------------------------------------------------------------------
// joint kernel: EXACT R6 structure (best measured: 429.4 us).
// BM=64, 256 threads, 2 CTAs/SM, 2-stage double buffer, chunk-0 pre-issued.
// ---------------------------------------------------------------------------
#define A_BYTES   65536
#define B_CHUNK   16384
#define OFF_A     0
#define OFF_B     A_BYTES
#define SMEM_TOTAL (A_BYTES + 2 * B_CHUNK)   // 98304

__global__ void __launch_bounds__(256, 2)
joint_kernel(const float* __restrict__ gamma, const float* __restrict__ beta,
             const float* __restrict__ b_out, float* __restrict__ out)
{
    extern __shared__ __align__(1024) char smem[];
    const uint32_t smemU = smem_u32(smem);
    const uint32_t Bs_u  = smemU + OFF_B;

    const int bt   = blockIdx.x >> 1;
    const int half = blockIdx.x & 1;
    const int bb   = bt >> 8;
    const int tid  = threadIdx.x;
    const int w    = tid >> 5, lane = tid & 31;

    // stage enc/gamma/beta in buf1 region (overwritten later by B chunk kc=1)
    float* encS   = (float*)(smem + OFF_B + B_CHUNK);
    float* gammaS = encS + 512;
    float* betaS  = gammaS + 512;

    // B load lane mapping: 4 cp16 per thread per chunk; swizzle invariant in p
    const int nrL  = tid >> 2;
    const int segL = tid & 3;
    const uint32_t dstL = (uint32_t)(nrL * 64 + ((segL ^ ((nrL >> 1) & 3)) << 4));
    const __half* srcL = g_wout + (size_t)nrL * HH + (segL << 3);

    // ---- issue B chunk 0 (tile 0) load now; overlaps phase 1 compute ----
    #pragma unroll
    for (int p = 0; p < 4; p++)
        cp16(Bs_u + dstL + (uint32_t)(p << 12), srcL + (size_t)(p << 6) * HH);
    asm volatile("cp.async.commit_group;");

    for (int i = tid; i < 512; i += 256) {
        encS[i]   = g_enc[(size_t)bt * HH + i];
        gammaS[i] = gamma[i];
        betaS[i]  = beta[i];
    }
    __syncthreads();

    // ---- Phase 1: A = LN(relu(enc+pred)), fp16, XOR-swizzled rows ----
    #pragma unroll
    for (int r = 0; r < 8; r++) {
        const int u  = r * 8 + w;
        const int ug = half * 64 + u;
        const float* pr = g_pred + ((size_t)(bb * UU + ug)) * HH;
        float v[16];
        float s = 0.f, s2 = 0.f;
        #pragma unroll
        for (int i = 0; i < 16; i++) {
            int h = lane + (i << 5);
            float x = encS[h] + pr[h];
            x = fmaxf(x, 0.f);
            v[i] = x; s += x; s2 += x * x;
        }
        #pragma unroll
        for (int o = 16; o; o >>= 1) {
            s  += __shfl_xor_sync(0xffffffffu, s,  o);
            s2 += __shfl_xor_sync(0xffffffffu, s2, o);
        }
        float mean = s * (1.f / 512.f);
        float var  = fmaxf(s2 * (1.f / 512.f) - mean * mean, 0.f);
        float rstd = rsqrtf(var + EPSV);
        const uint32_t xr = (uint32_t)((u & 7) << 4);
        #pragma unroll
        for (int i = 0; i < 16; i++) {
            int h = lane + (i << 5);
            uint32_t off = (uint32_t)(u * 1024) + ((uint32_t)((h >> 3) << 4) ^ xr)
                         + (uint32_t)((h & 7) << 1);
            *(__half*)(smem + OFF_A + off) =
                __float2half((v[i] - mean) * rstd * gammaS[h] + betaS[h]);
        }
    }

    // ---- Phase 2: GEMM 64x1024x512, nested tiles ----
    const int warpM = w & 1;
    const int warpN = w >> 1;

    const int rowA0 = warpM * 32 + (lane & 15);
    const uint32_t aBase = smemU + OFF_A + (uint32_t)(rowA0 * 1024);
    const uint32_t xorA  = (uint32_t)((rowA0 & 7) << 4);
    const uint32_t klane = (uint32_t)((lane >> 4) << 4);

    const int nLaneRow = (lane & 7) + ((lane >> 4) << 3);
    const int khalf    = (lane >> 3) & 1;
    uint32_t bBase[4], bXor[4];
    #pragma unroll
    for (int j = 0; j < 4; j++) {
        const int n = warpN * 64 + j * 16 + nLaneRow;
        bBase[j] = (uint32_t)(n * 64);
        bXor[j]  = (uint32_t)(((n >> 1) & 3) << 4);
    }

    float acc[2][8][4];
    const size_t outBase = (size_t)bt * (UU * VV) + (size_t)half * 64 * VV;

    for (int no = 0; no < 4; no++) {
        const int n0 = no << 8;
        #pragma unroll
        for (int mi = 0; mi < 2; mi++)
            #pragma unroll
            for (int ni = 0; ni < 8; ni++)
                #pragma unroll
                for (int q = 0; q < 4; q++) acc[mi][ni][q] = 0.f;

        // chunk 0 of this tile is in flight (pre-phase-1 or prior tile tail)
        asm volatile("cp.async.wait_group 0;" ::: "memory");
        __syncthreads();

        for (int kc = 0; kc < 16; kc++) {
            const int buf = kc & 1;
            // prefetch next chunk (kc+1 of this tile, or chunk 0 of next tile)
            if (kc < 15 || no < 3) {
                const int kn  = (kc < 15) ? ((kc + 1) << 5) : 0;
                const int n0l = (kc < 15) ? n0 : (n0 + 256);
                const uint32_t dstBase = Bs_u + (uint32_t)((buf ^ 1) * B_CHUNK) + dstL;
                #pragma unroll
                for (int p = 0; p < 4; p++)
                    cp16(dstBase + (uint32_t)(p << 12),
                         srcL + (size_t)(n0l + (p << 6)) * HH + kn);
                asm volatile("cp.async.commit_group;");
            }
            const int kglob = kc << 5;
            const uint32_t bufB = Bs_u + (uint32_t)(buf * B_CHUNK);
            #pragma unroll
            for (int kk2 = 0; kk2 < 2; kk2++) {
                const int kk = kk2 << 4;
                const uint32_t aOff = (((uint32_t)((kglob + kk) << 1) + klane) ^ xorA);
                uint32_t a[2][4];
                ldmX4(a[0], aBase + aOff);
                ldmX4(a[1], aBase + 16384u + aOff);
                const uint32_t seg16 = (uint32_t)((kk2 << 1) + khalf) << 4;
                uint32_t bf[4][4];
                #pragma unroll
                for (int j = 0; j < 4; j++)
                    ldmX4(bf[j], bufB + bBase[j] + (seg16 ^ bXor[j]));
                #pragma unroll
                for (int mi = 0; mi < 2; mi++)
                    #pragma unroll
                    for (int ni = 0; ni < 8; ni++)
                        mma16816(acc[mi][ni], a[mi],
                                 bf[ni >> 1][(ni & 1) * 2],
                                 bf[ni >> 1][(ni & 1) * 2 + 1]);
            }
            if (kc < 15) {
                asm volatile("cp.async.wait_group 0;" ::: "memory");
                __syncthreads();
            }
        }

        // epilogue (next tile's chunk-0 load already in flight)
        #pragma unroll
        for (int mi = 0; mi < 2; mi++) {
            const int row = warpM * 32 + mi * 16 + (lane >> 2);
            #pragma unroll
            for (int ni = 0; ni < 8; ni++) {
                const int col = n0 + warpN * 64 + ni * 8 + ((lane & 3) << 1);
                const float2 bo = __ldg(reinterpret_cast<const float2*>(b_out + col));
                float2 v0 = make_float2(acc[mi][ni][0] + bo.x, acc[mi][ni][1] + bo.y);
                float2 v1 = make_float2(acc[mi][ni][2] + bo.x, acc[mi][ni][3] + bo.y);
                *reinterpret_cast<float2*>(out + outBase + (size_t)row * VV + col)       = v0;
                *reinterpret_cast<float2*>(out + outBase + (size_t)(row + 8) * VV + col) = v1;
            }
        }
    }
}

// ---------------------------------------------------------------------------
extern "C" void kernel_launch(void* const* d_in, const int* in_sizes, int n_in,
                              void* d_out, int out_size)
{
    (void)in_sizes; (void)n_in; (void)out_size;
    const float* enc_in  = (const float*)d_in[0];
    const float* pred_in = (const float*)d_in[1];
    const float* W_enc   = (const float*)d_in[2];
    const float* b_enc   = (const float*)d_in[3];
    const float* W_pred  = (const float*)d_in[4];
    const float* b_pred  = (const float*)d_in[5];
    const float* gamma   = (const float*)d_in[6];
    const float* beta    = (const float*)d_in[7];
    const float* W_out   = (const float*)d_in[8];
    const float* b_out   = (const float*)d_in[9];
    float* out = (float*)d_out;

    float* enc_ptr = nullptr;
    float* pred_ptr = nullptr;
    cudaGetSymbolAddress((void**)&enc_ptr,  g_enc);
    cudaGetSymbolAddress((void**)&pred_ptr, g_pred);

    prep_kernel<<<256, 256>>>(enc_in, pred_in, W_enc, b_enc, W_pred, b_pred,
                              W_out, enc_ptr, pred_ptr);

    cudaFuncSetAttribute(joint_kernel, cudaFuncAttributeMaxDynamicSharedMemorySize,
                         SMEM_TOTAL);
    joint_kernel<<<BB * TT * 2, 256, SMEM_TOTAL>>>(gamma, beta, b_out, out);
}

// round 10
// speedup vs baseline: 1.7678x; 1.1114x over previous
#include <cuda_runtime.h>
#include <cuda_fp16.h>
#include <cuda_bf16.h>
#include <cstdint>

#define BB 4
#define TT 256
#define UU 128
#define D_ENC 512
#define D_PRED 640
#define HH 512
#define VV 1024
#define EPSV 1e-5f

// Device scratch
__device__ float  g_enc [BB * TT * HH];
__device__ float  g_pred[BB * UU * HH];
__device__ __half g_wout[VV * HH];      // fp16 copy of W_out, [v][h]

// ---------------------------------------------------------------------------
// Fused prep kernel v2: register-staged, BK=32 double buffer.
// blocks [0,128) enc, [128,192) pred, [192,256) W_out convert.
// ---------------------------------------------------------------------------
__device__ __forceinline__ void proj_body(const float* __restrict__ X,
                                          const float* __restrict__ W,
                                          const float* __restrict__ bias,
                                          float* __restrict__ C,
                                          int m0, int n0, int N, int K,
                                          float Xs[2][32][65], float Ws[2][32][65])
{
    const int tid = threadIdx.x;
    const int ty = tid >> 4, tx = tid & 15;
    const int rL = tid >> 5;
    const int cL = tid & 31;

    float xr[8], wr[8];
    #pragma unroll
    for (int p = 0; p < 8; p++) {
        xr[p] = X[(size_t)(m0 + p * 8 + rL) * K + cL];
        wr[p] = W[(size_t)(n0 + p * 8 + rL) * K + cL];
    }

    float acc[4][4];
    #pragma unroll
    for (int i = 0; i < 4; i++)
        #pragma unroll
        for (int j = 0; j < 4; j++) acc[i][j] = 0.f;

    const int NK = K >> 5;
    for (int t = 0; t < NK; t++) {
        const int buf = t & 1;
        #pragma unroll
        for (int p = 0; p < 8; p++) {
            Xs[buf][cL][p * 8 + rL] = xr[p];
            Ws[buf][cL][p * 8 + rL] = wr[p];
        }
        __syncthreads();
        if (t + 1 < NK) {
            const int k0 = (t + 1) << 5;
            #pragma unroll
            for (int p = 0; p < 8; p++) {
                xr[p] = X[(size_t)(m0 + p * 8 + rL) * K + k0 + cL];
                wr[p] = W[(size_t)(n0 + p * 8 + rL) * K + k0 + cL];
            }
        }
        #pragma unroll
        for (int kk = 0; kk < 32; kk++) {
            float a[4], b[4];
            #pragma unroll
            for (int i = 0; i < 4; i++) a[i] = Xs[buf][kk][ty * 4 + i];
            #pragma unroll
            for (int j = 0; j < 4; j++) b[j] = Ws[buf][kk][tx * 4 + j];
            #pragma unroll
            for (int i = 0; i < 4; i++)
                #pragma unroll
                for (int j = 0; j < 4; j++) acc[i][j] = fmaf(a[i], b[j], acc[i][j]);
        }
    }
    #pragma unroll
    for (int i = 0; i < 4; i++)
        #pragma unroll
        for (int j = 0; j < 4; j++) {
            int m = m0 + ty * 4 + i, n = n0 + tx * 4 + j;
            C[(size_t)m * N + n] = acc[i][j] + bias[n];
        }
}

__global__ void __launch_bounds__(256)
prep_kernel(const float* __restrict__ enc_in, const float* __restrict__ pred_in,
            const float* __restrict__ W_enc, const float* __restrict__ b_enc,
            const float* __restrict__ W_pred, const float* __restrict__ b_pred,
            const float* __restrict__ W_out,
            float* __restrict__ enc_out, float* __restrict__ pred_out)
{
    __shared__ float Xs[2][32][65];
    __shared__ float Ws[2][32][65];
    const int blk = blockIdx.x;
    if (blk < 128) {
        proj_body(enc_in, W_enc, b_enc, enc_out,
                  (blk >> 3) * 64, (blk & 7) * 64, HH, D_ENC, Xs, Ws);
    } else if (blk < 192) {
        const int t = blk - 128;
        proj_body(pred_in, W_pred, b_pred, pred_out,
                  (t >> 3) * 64, (t & 7) * 64, HH, D_PRED, Xs, Ws);
    } else {
        const int t = blk - 192;
        const int tid = threadIdx.x;
        #pragma unroll
        for (int j = 0; j < 8; j++) {
            int idx = t * 8192 + j * 1024 + tid * 4;
            float4 v = *reinterpret_cast<const float4*>(W_out + idx);
            __half2 h01 = __floats2half2_rn(v.x, v.y);
            __half2 h23 = __floats2half2_rn(v.z, v.w);
            uint2 pk;
            pk.x = *reinterpret_cast<uint32_t*>(&h01);
            pk.y = *reinterpret_cast<uint32_t*>(&h23);
            *reinterpret_cast<uint2*>(&g_wout[idx]) = pk;
        }
    }
}

// ---------------------------------------------------------------------------
// mma.sync helpers
// ---------------------------------------------------------------------------
__device__ __forceinline__ uint32_t smem_u32(const void* p) {
    return (uint32_t)__cvta_generic_to_shared(p);
}
__device__ __forceinline__ void ldmX4(uint32_t a[4], uint32_t addr) {
    asm volatile("ldmatrix.sync.aligned.m8n8.x4.shared.b16 {%0,%1,%2,%3}, [%4];"
                 : "=r"(a[0]), "=r"(a[1]), "=r"(a[2]), "=r"(a[3]) : "r"(addr));
}
__device__ __forceinline__ void mma16816(float c[4], const uint32_t a[4],
                                         uint32_t b0, uint32_t b1) {
    asm volatile(
        "mma.sync.aligned.m16n8k16.row.col.f32.f16.f16.f32 "
        "{%0,%1,%2,%3}, {%4,%5,%6,%7}, {%8,%9}, {%0,%1,%2,%3};"
        : "+f"(c[0]), "+f"(c[1]), "+f"(c[2]), "+f"(c[3])
        : "r"(a[0]), "r"(a[1]), "r"(a[2]), "r"(a[3]), "r"(b0), "r"(b1));
}
__device__ __forceinline__ void cp16(uint32_t dst, const void* src) {
    asm volatile("cp.async.cg.shared.global [%0], [%1], 16;" :: "r"(dst), "l"(src));
}
__device__ __forceinline__ void bar64(int id) {
    asm volatile("bar.sync %0, 64;" :: "r"(id) : "memory");
}

// ---------------------------------------------------------------------------
// joint kernel: BM=64, 256 threads, 2 CTAs/SM.
// NEW: per-warpN-pair private B double buffers (2 x 4 KB each) synced with
// named barriers (64 threads) -- no block-wide barriers in the k-loop.
// A: XOR-swizzled fp16 [64][512] (64 KB), one __syncthreads after phase 1.
// ---------------------------------------------------------------------------
#define A_BYTES    65536
#define PAIR_BUF   4096                    // 64 rows x 64 B (k32 chunk)
#define OFF_B      A_BYTES                 // 4 pairs x 2 bufs x 4 KB = 32 KB
#define OFF_STAGE  (A_BYTES + 32768)       // enc/gamma/beta: 3 x 2 KB
#define SMEM_TOTAL (OFF_STAGE + 6144)      // 104448

__global__ void __launch_bounds__(256, 2)
joint_kernel(const float* __restrict__ gamma, const float* __restrict__ beta,
             const float* __restrict__ b_out, float* __restrict__ out)
{
    extern __shared__ __align__(1024) char smem[];
    const uint32_t smemU = smem_u32(smem);

    const int bt   = blockIdx.x >> 1;
    const int half = blockIdx.x & 1;
    const int bb   = bt >> 8;
    const int tid  = threadIdx.x;
    const int w    = tid >> 5, lane = tid & 31;
    const int warpM = w & 1;
    const int warpN = w >> 1;            // pair id 0..3
    const int pm    = warpM * 32 + lane; // thread id within pair 0..63

    float* encS   = (float*)(smem + OFF_STAGE);
    float* gammaS = encS + 512;
    float* betaS  = gammaS + 512;

    // pair-private B buffer base
    const uint32_t pairU = smemU + OFF_B + (uint32_t)(warpN * 2 * PAIR_BUF);

    // pair load mapping: thread pm covers row rowL (+16 per pass), seg segL
    const int rowL = pm >> 2;            // 0..15
    const int segL = pm & 3;
    const uint32_t dstL = (uint32_t)(rowL * 64 + ((segL ^ ((rowL >> 1) & 3)) << 4));
    const __half* srcL = g_wout + (size_t)(warpN * 64 + rowL) * HH + (segL << 3);

    // ---- preload chunk 0 (tile 0) into pair buf0; overlaps phase 1 ----
    #pragma unroll
    for (int p = 0; p < 4; p++)
        cp16(pairU + dstL + (uint32_t)(p << 10), srcL + (size_t)(p << 4) * HH);
    asm volatile("cp.async.commit_group;");

    for (int i = tid; i < 512; i += 256) {
        encS[i]   = g_enc[(size_t)bt * HH + i];
        gammaS[i] = gamma[i];
        betaS[i]  = beta[i];
    }
    __syncthreads();

    // ---- Phase 1: A = LN(relu(enc+pred)), fp16, XOR-swizzled rows ----
    #pragma unroll
    for (int r = 0; r < 8; r++) {
        const int u  = r * 8 + w;
        const int ug = half * 64 + u;
        const float* pr = g_pred + ((size_t)(bb * UU + ug)) * HH;
        float v[16];
        float s = 0.f, s2 = 0.f;
        #pragma unroll
        for (int i = 0; i < 16; i++) {
            int h = lane + (i << 5);
            float x = encS[h] + pr[h];
            x = fmaxf(x, 0.f);
            v[i] = x; s += x; s2 += x * x;
        }
        #pragma unroll
        for (int o = 16; o; o >>= 1) {
            s  += __shfl_xor_sync(0xffffffffu, s,  o);
            s2 += __shfl_xor_sync(0xffffffffu, s2, o);
        }
        float mean = s * (1.f / 512.f);
        float var  = fmaxf(s2 * (1.f / 512.f) - mean * mean, 0.f);
        float rstd = rsqrtf(var + EPSV);
        const uint32_t xr = (uint32_t)((u & 7) << 4);
        #pragma unroll
        for (int i = 0; i < 16; i++) {
            int h = lane + (i << 5);
            uint32_t off = (uint32_t)(u * 1024) + ((uint32_t)((h >> 3) << 4) ^ xr)
                         + (uint32_t)((h & 7) << 1);
            *(__half*)(smem + off) =
                __float2half((v[i] - mean) * rstd * gammaS[h] + betaS[h]);
        }
    }
    __syncthreads();   // A visible to all warps; after this, pairs run free

    // ---- Phase 2: GEMM 64x1024x512, pair-decoupled pipeline ----
    const int rowA0 = warpM * 32 + (lane & 15);
    const uint32_t aBase = smemU + (uint32_t)(rowA0 * 1024);
    const uint32_t xorA  = (uint32_t)((rowA0 & 7) << 4);
    const uint32_t klane = (uint32_t)((lane >> 4) << 4);

    const int nLaneRow = (lane & 7) + ((lane >> 4) << 3);   // 0..15 local
    const int khalf    = (lane >> 3) & 1;
    uint32_t bBase[4], bXor[4];
    #pragma unroll
    for (int j = 0; j < 4; j++) {
        const int nloc = j * 16 + nLaneRow;        // local row in pair buffer
        bBase[j] = (uint32_t)(nloc * 64);
        bXor[j]  = (uint32_t)(((nloc >> 1) & 3) << 4);
    }
    const int barid = warpN + 1;

    float acc[2][8][4];
    const size_t outBase = (size_t)bt * (UU * VV) + (size_t)half * 64 * VV;

    for (int no = 0; no < 4; no++) {
        const int n0 = no << 8;
        #pragma unroll
        for (int mi = 0; mi < 2; mi++)
            #pragma unroll
            for (int ni = 0; ni < 8; ni++)
                #pragma unroll
                for (int q = 0; q < 4; q++) acc[mi][ni][q] = 0.f;

        // current tile's chunk 0 is in flight (preload or prior tile's tail)
        asm volatile("cp.async.wait_group 0;" ::: "memory");
        bar64(barid);

        for (int kc = 0; kc < 16; kc++) {
            const int buf = kc & 1;
            // prefetch next chunk (kc+1 of this tile, or chunk 0 of next tile)
            if (kc < 15 || no < 3) {
                const int kn  = (kc < 15) ? ((kc + 1) << 5) : 0;
                const int n0l = (kc < 15) ? n0 : (n0 + 256);
                const uint32_t dstBase = pairU + (uint32_t)((buf ^ 1) * PAIR_BUF) + dstL;
                #pragma unroll
                for (int p = 0; p < 4; p++)
                    cp16(dstBase + (uint32_t)(p << 10),
                         srcL + (size_t)(n0l + (p << 4)) * HH + kn);
                asm volatile("cp.async.commit_group;");
            }
            const int kglob = kc << 5;
            const uint32_t bufB = pairU + (uint32_t)(buf * PAIR_BUF);
            #pragma unroll
            for (int kk2 = 0; kk2 < 2; kk2++) {
                const int kk = kk2 << 4;
                const uint32_t aOff = (((uint32_t)((kglob + kk) << 1) + klane) ^ xorA);
                uint32_t a[2][4];
                ldmX4(a[0], aBase + aOff);
                ldmX4(a[1], aBase + 16384u + aOff);
                const uint32_t seg16 = (uint32_t)((kk2 << 1) + khalf) << 4;
                uint32_t bf[4][4];
                #pragma unroll
                for (int j = 0; j < 4; j++)
                    ldmX4(bf[j], bufB + bBase[j] + (seg16 ^ bXor[j]));
                #pragma unroll
                for (int mi = 0; mi < 2; mi++)
                    #pragma unroll
                    for (int ni = 0; ni < 8; ni++)
                        mma16816(acc[mi][ni], a[mi],
                                 bf[ni >> 1][(ni & 1) * 2],
                                 bf[ni >> 1][(ni & 1) * 2 + 1]);
            }
            if (kc < 15) {
                asm volatile("cp.async.wait_group 0;" ::: "memory");
                bar64(barid);
            }
        }

        // epilogue (pair-local; next tile's chunk-0 load already in flight)
        #pragma unroll
        for (int mi = 0; mi < 2; mi++) {
            const int row = warpM * 32 + mi * 16 + (lane >> 2);
            #pragma unroll
            for (int ni = 0; ni < 8; ni++) {
                const int col = n0 + warpN * 64 + ni * 8 + ((lane & 3) << 1);
                const float2 bo = __ldg(reinterpret_cast<const float2*>(b_out + col));
                float2 v0 = make_float2(acc[mi][ni][0] + bo.x, acc[mi][ni][1] + bo.y);
                float2 v1 = make_float2(acc[mi][ni][2] + bo.x, acc[mi][ni][3] + bo.y);
                *reinterpret_cast<float2*>(out + outBase + (size_t)row * VV + col)       = v0;
                *reinterpret_cast<float2*>(out + outBase + (size_t)(row + 8) * VV + col) = v1;
            }
        }
    }
}

// ---------------------------------------------------------------------------
extern "C" void kernel_launch(void* const* d_in, const int* in_sizes, int n_in,
                              void* d_out, int out_size)
{
    (void)in_sizes; (void)n_in; (void)out_size;
    const float* enc_in  = (const float*)d_in[0];
    const float* pred_in = (const float*)d_in[1];
    const float* W_enc   = (const float*)d_in[2];
    const float* b_enc   = (const float*)d_in[3];
    const float* W_pred  = (const float*)d_in[4];
    const float* b_pred  = (const float*)d_in[5];
    const float* gamma   = (const float*)d_in[6];
    const float* beta    = (const float*)d_in[7];
    const float* W_out   = (const float*)d_in[8];
    const float* b_out   = (const float*)d_in[9];
    float* out = (float*)d_out;

    float* enc_ptr = nullptr;
    float* pred_ptr = nullptr;
    cudaGetSymbolAddress((void**)&enc_ptr,  g_enc);
    cudaGetSymbolAddress((void**)&pred_ptr, g_pred);

    prep_kernel<<<256, 256>>>(enc_in, pred_in, W_enc, b_enc, W_pred, b_pred,
                              W_out, enc_ptr, pred_ptr);

    cudaFuncSetAttribute(joint_kernel, cudaFuncAttributeMaxDynamicSharedMemorySize,
                         SMEM_TOTAL);
    joint_kernel<<<BB * TT * 2, 256, SMEM_TOTAL>>>(gamma, beta, b_out, out);
}